// round 2
// baseline (speedup 1.0000x reference)
#include <cuda_runtime.h>
#include <math.h>

#define QF 512.0f
#define ROWS_PER_BLOCK 64
#define THREADS 256

// c(x) = coth(x) - 1/x, cox = c(x)/x.  Stable for all x (odd, smooth at 0).
__device__ __forceinline__ void cfun(float x, float& c, float& cox) {
    float ax = fabsf(x);
    if (ax < 0.5f) {
        float x2 = x * x;
        cox = 0.33333334f + x2 * (-0.022222223f + x2 * (0.0021164021f + x2 * (-2.1164021e-4f)));
        c = x * cox;
    } else {
        float e = __expf(2.0f * x);
        float coth = isinf(e) ? 1.0f : __fdividef(e + 1.0f, e - 1.0f);
        float ix = __fdividef(1.0f, x);
        c = coth - ix;
        cox = c * ix;
    }
}

// mean index and variance index of exp-tilted distribution on {0..Q-1}, t = lambda*h
__device__ __forceinline__ void moments(float t, float& mu, float& var) {
    float c1, c1x, cQ, cQx;
    cfun(0.5f * t, c1, c1x);
    cfun(256.0f * t, cQ, cQx);
    mu = 255.5f + 0.5f * (QF * cQ - c1);
    float cp1 = 1.0f - 2.0f * c1x - c1 * c1;
    float cpQ = 1.0f - 2.0f * cQx - cQ * cQ;
    var = 0.25f * (262144.0f * cpQ - cp1);
}

__global__ void __launch_bounds__(THREADS)
fused_kernel(const float* __restrict__ vel, const float* __restrict__ xi,
             float* __restrict__ out, int n) {
    __shared__ float s_lam[ROWS_PER_BLOCK];
    __shared__ float s_mu0[ROWS_PER_BLOCK];
    __shared__ float s_r[ROWS_PER_BLOCK];
    __shared__ float s_R[ROWS_PER_BLOCK];

    int tid = threadIdx.x;
    int base = blockIdx.x * ROWS_PER_BLOCK;
    float h = xi[1] - xi[0];                       // 70/511 (L1/L2-hot after block 0)

    // ---- Phase 1: threads 0..63 each solve one row (dense Newton, closed-form moments)
    if (tid < ROWS_PER_BLOCK) {
        int row = base + tid;
        if (row < n) {
            float target = __fdividef(vel[row], h);   // target mean index
            float t = 0.0f;
            #pragma unroll 1
            for (int it = 0; it < 12; ++it) {
                float mu, var;
                moments(t, mu, var);
                t -= __fdividef(mu - target, var);
                t = fminf(0.06f, fmaxf(-0.06f, t));   // true root |t| <= ~0.028
            }
            // logS0 = log((e^{Qt}-1)/(e^t-1)), stable via expm1 (once per row, accurate path)
            float logS0;
            if (fabsf(t) < 1e-12f) {
                logS0 = logf(QF) + 255.5f * t;
            } else {
                logS0 = logf(expm1f(QF * t) / expm1f(t));
            }
            s_lam[tid] = t / h;
            s_mu0[tid] = -logS0;
            s_r[tid]   = expf(t);
            s_R[tid]   = expf(128.0f * t);
        }
    }
    __syncthreads();

    // ---- Phase 2: each warp writes 8 rows. Lane l owns j = 4l + 128k (coalesced float4).
    int warpid = tid >> 5;
    int lane = tid & 31;
    float xiv = __ldg(&xi[lane << 2]);             // anchor xi value for this lane

    #pragma unroll 1
    for (int rr = 0; rr < 8; ++rr) {
        int rl = warpid * 8 + rr;
        int row = base + rl;
        if (row >= n) break;
        float lam = s_lam[rl];                     // broadcast reads, no conflicts
        float mu0 = s_mu0[rl];
        float r  = s_r[rl];
        float R  = s_R[rl];
        float r2 = r * r;
        float r3 = r2 * r;
        float v = expf(fmaf(lam, xiv, mu0));       // one accurate anchor per lane
        float4* o = reinterpret_cast<float4*>(out) + (size_t)row * 128;
        #pragma unroll
        for (int k = 0; k < 4; ++k) {
            __stcs(&o[lane + (k << 5)], make_float4(v, v * r, v * r2, v * r3));
            v *= R;
        }
    }
}

extern "C" void kernel_launch(void* const* d_in, const int* in_sizes, int n_in,
                              void* d_out, int out_size) {
    const float* vel = (const float*)d_in[0];
    const float* xi  = (const float*)d_in[1];
    int n = in_sizes[0];
    if (n_in >= 2 && in_sizes[0] < in_sizes[1]) {   // defensive: xi is the small (Q) buffer
        vel = (const float*)d_in[1];
        xi  = (const float*)d_in[0];
        n = in_sizes[1];
    }
    float* out = (float*)d_out;
    int blocks = (n + ROWS_PER_BLOCK - 1) / ROWS_PER_BLOCK;
    fused_kernel<<<blocks, THREADS>>>(vel, xi, out, n);
}

// round 3
// speedup vs baseline: 1.0604x; 1.0604x over previous
#include <cuda_runtime.h>
#include <math.h>

#define QF 512.0f
#define ROWS_PER_WARP 8
#define THREADS 256
#define ROWS_PER_BLOCK (ROWS_PER_WARP * (THREADS / 32))   // 64

// c(x) = coth(x) - 1/x, cox = c(x)/x.  Stable for all x (odd, smooth at 0).
__device__ __forceinline__ void cfun(float x, float& c, float& cox) {
    float ax = fabsf(x);
    if (ax < 0.5f) {
        float x2 = x * x;
        cox = 0.33333334f + x2 * (-0.022222223f + x2 * (0.0021164021f + x2 * (-2.1164021e-4f)));
        c = x * cox;
    } else {
        float e = __expf(2.0f * x);
        float coth = isinf(e) ? 1.0f : __fdividef(e + 1.0f, e - 1.0f);
        float ix = __fdividef(1.0f, x);
        c = coth - ix;
        cox = c * ix;
    }
}

// mean index and variance index of exp-tilted distribution on {0..Q-1}, t = lambda*h
__device__ __forceinline__ void moments(float t, float& mu, float& var) {
    float c1, c1x, cQ, cQx;
    cfun(0.5f * t, c1, c1x);
    cfun(256.0f * t, cQ, cQx);
    mu = 255.5f + 0.5f * (QF * cQ - c1);
    float cp1 = 1.0f - 2.0f * c1x - c1 * c1;
    float cpQ = 1.0f - 2.0f * cQx - cQ * cQ;
    var = 0.25f * (262144.0f * cpQ - cp1);
}

// log(sinh(x)/x), stable for all x, fast-math
__device__ __forceinline__ float log_sinhc(float x) {
    float ax = fabsf(x);
    if (ax < 0.5f) {
        float x2 = x * x;
        return x2 * (0.16666667f - x2 * 0.0055555556f);   // x^2/6 - x^4/180
    }
    float s = 0.5f * (__expf(ax) - __expf(-ax));          // sinh, no cancellation in log
    return __logf(__fdividef(s, ax));
}

__global__ void __launch_bounds__(THREADS)
fused_kernel(const float* __restrict__ vel, const float* __restrict__ xi,
             float* __restrict__ out, int n) {
    int tid = threadIdx.x;
    int warpid = tid >> 5;
    int lane = tid & 31;
    int rowbase = blockIdx.x * ROWS_PER_BLOCK + warpid * ROWS_PER_WARP;
    if (rowbase >= n) return;

    float h = __ldg(&xi[1]) - __ldg(&xi[0]);      // 70/511, L1-hot

    // ---- Solve: lanes 0..7 each own one row; no smem, no __syncthreads ----
    float lam = 0.0f, mu0 = 0.0f, r = 1.0f, R = 1.0f;
    if (lane < ROWS_PER_WARP && rowbase + lane < n) {
        float target = __fdividef(__ldg(&vel[rowbase + lane]), h);  // mean index
        // init: inverse Langevin (Cohen) on y = c(256 t), ~5% accurate
        float y = (target - 255.5f) * (1.0f / 256.0f);
        y = fminf(0.92f, fmaxf(-0.92f, y));
        float t = y * __fdividef(3.0f - y * y, 1.0f - y * y) * (1.0f / 256.0f);
        #pragma unroll
        for (int it = 0; it < 4; ++it) {          // quadratic: 5e-2 -> fp32 noise in 3
            float mu, var;
            moments(t, mu, var);
            t -= __fdividef(mu - target, var);
            t = fminf(0.06f, fmaxf(-0.06f, t));   // true root |t| <= ~0.028
        }
        // logS0 = log512 + 255.5 t + log sinhc(256t) - log sinhc(t/2)
        float u = 0.5f * t;
        float logS0 = 6.2383246f + 255.5f * t + log_sinhc(256.0f * t)
                      - u * u * 0.16666667f;      // log sinhc(u) ~ u^2/6, u<=0.015
        lam = t / h;
        mu0 = -logS0;
        r = __expf(t);
        R = __expf(128.0f * t);
    }

    // ---- Write: warp streams its 8 rows; lane l owns j = 4l + 128k (coalesced float4)
    float xiv = __ldg(&xi[lane << 2]);
    #pragma unroll 1
    for (int rr = 0; rr < ROWS_PER_WARP; ++rr) {
        int row = rowbase + rr;
        if (row >= n) break;
        float lamr = __shfl_sync(0xffffffffu, lam, rr);
        float mu0r = __shfl_sync(0xffffffffu, mu0, rr);
        float rA   = __shfl_sync(0xffffffffu, r,   rr);
        float RA   = __shfl_sync(0xffffffffu, R,   rr);
        float r2 = rA * rA;
        float r3 = r2 * rA;
        float v = __expf(fmaf(lamr, xiv, mu0r));  // anchor per lane
        float4* o = reinterpret_cast<float4*>(out) + (size_t)row * 128;
        #pragma unroll
        for (int k = 0; k < 4; ++k) {
            __stcs(&o[lane + (k << 5)], make_float4(v, v * rA, v * r2, v * r3));
            v *= RA;
        }
    }
}

extern "C" void kernel_launch(void* const* d_in, const int* in_sizes, int n_in,
                              void* d_out, int out_size) {
    const float* vel = (const float*)d_in[0];
    const float* xi  = (const float*)d_in[1];
    int n = in_sizes[0];
    if (n_in >= 2 && in_sizes[0] < in_sizes[1]) {   // defensive: xi is the small (Q) buffer
        vel = (const float*)d_in[1];
        xi  = (const float*)d_in[0];
        n = in_sizes[1];
    }
    float* out = (float*)d_out;
    int blocks = (n + ROWS_PER_BLOCK - 1) / ROWS_PER_BLOCK;
    fused_kernel<<<blocks, THREADS>>>(vel, xi, out, n);
}

// round 4
// speedup vs baseline: 1.1443x; 1.0792x over previous
#include <cuda_runtime.h>
#include <math.h>

#define QF 512.0f
#define ROWS_PER_WARP 2
#define THREADS 256
#define ROWS_PER_BLOCK (ROWS_PER_WARP * (THREADS / 32))   // 16

// c(x) = coth(x) - 1/x, cox = c(x)/x.  Stable for all x (odd, smooth at 0).
__device__ __forceinline__ void cfun(float x, float& c, float& cox) {
    float ax = fabsf(x);
    if (ax < 0.5f) {
        float x2 = x * x;
        cox = 0.33333334f + x2 * (-0.022222223f + x2 * (0.0021164021f + x2 * (-2.1164021e-4f)));
        c = x * cox;
    } else {
        float e = __expf(2.0f * x);
        float coth = isinf(e) ? 1.0f : __fdividef(e + 1.0f, e - 1.0f);
        float ix = __fdividef(1.0f, x);
        c = coth - ix;
        cox = c * ix;
    }
}

// mean index and variance index of exp-tilted distribution on {0..Q-1}, t = lambda*h
__device__ __forceinline__ void moments(float t, float& mu, float& var) {
    float c1, c1x, cQ, cQx;
    cfun(0.5f * t, c1, c1x);
    cfun(256.0f * t, cQ, cQx);
    mu = 255.5f + 0.5f * (QF * cQ - c1);
    float cp1 = 1.0f - 2.0f * c1x - c1 * c1;
    float cpQ = 1.0f - 2.0f * cQx - cQ * cQ;
    var = 0.25f * (262144.0f * cpQ - cp1);
}

// log(sinh(x)/x), stable for all x, fast-math
__device__ __forceinline__ float log_sinhc(float x) {
    float ax = fabsf(x);
    if (ax < 0.5f) {
        float x2 = x * x;
        return x2 * (0.16666667f - x2 * 0.0055555556f);   // x^2/6 - x^4/180
    }
    float s = 0.5f * (__expf(ax) - __expf(-ax));
    return __logf(__fdividef(s, ax));
}

__global__ void __launch_bounds__(THREADS)
fused_kernel(const float* __restrict__ vel, const float* __restrict__ xi,
             float* __restrict__ out, int n) {
    int tid = threadIdx.x;
    int warpid = tid >> 5;
    int lane = tid & 31;
    int rowbase = blockIdx.x * ROWS_PER_BLOCK + warpid * ROWS_PER_WARP;
    if (rowbase >= n) return;

    float h = __ldg(&xi[1]) - __ldg(&xi[0]);      // 70/511, L1-hot

    // ---- Solve: lanes 0..1 each own one row; no smem, no barrier ----
    float lam = 0.0f, mu0 = 0.0f, r = 1.0f, R = 1.0f;
    if (lane < ROWS_PER_WARP && rowbase + lane < n) {
        float target = __fdividef(__ldg(&vel[rowbase + lane]), h);  // mean index
        // init: inverse Langevin (Cohen) on y = c(256 t), ~5% accurate
        float y = (target - 255.5f) * (1.0f / 256.0f);
        y = fminf(0.92f, fmaxf(-0.92f, y));
        float t = y * __fdividef(3.0f - y * y, 1.0f - y * y) * (1.0f / 256.0f);
        #pragma unroll
        for (int it = 0; it < 4; ++it) {          // quadratic: 5e-2 -> fp32 noise in 3
            float mu, var;
            moments(t, mu, var);
            t -= __fdividef(mu - target, var);
            t = fminf(0.06f, fmaxf(-0.06f, t));   // true root |t| <= ~0.028
        }
        // logS0 = log512 + 255.5 t + log sinhc(256t) - log sinhc(t/2)
        float u = 0.5f * t;
        float logS0 = 6.2383246f + 255.5f * t + log_sinhc(256.0f * t)
                      - u * u * 0.16666667f;
        lam = t / h;
        mu0 = -logS0;
        r = __expf(t);
        R = __expf(128.0f * t);
    }

    // ---- Write: warp streams its 2 rows; lane l owns j = 4l + 128k (coalesced float4)
    float xiv = __ldg(&xi[lane << 2]);
    #pragma unroll
    for (int rr = 0; rr < ROWS_PER_WARP; ++rr) {
        int row = rowbase + rr;
        if (row >= n) break;
        float lamr = __shfl_sync(0xffffffffu, lam, rr);
        float mu0r = __shfl_sync(0xffffffffu, mu0, rr);
        float rA   = __shfl_sync(0xffffffffu, r,   rr);
        float RA   = __shfl_sync(0xffffffffu, R,   rr);
        float r2 = rA * rA;
        float r3 = r2 * rA;
        float v = __expf(fmaf(lamr, xiv, mu0r));  // anchor per lane
        float4* o = reinterpret_cast<float4*>(out) + (size_t)row * 128;
        #pragma unroll
        for (int k = 0; k < 4; ++k) {
            __stcs(&o[lane + (k << 5)], make_float4(v, v * rA, v * r2, v * r3));
            v *= RA;
        }
    }
}

extern "C" void kernel_launch(void* const* d_in, const int* in_sizes, int n_in,
                              void* d_out, int out_size) {
    const float* vel = (const float*)d_in[0];
    const float* xi  = (const float*)d_in[1];
    int n = in_sizes[0];
    if (n_in >= 2 && in_sizes[0] < in_sizes[1]) {   // defensive: xi is the small (Q) buffer
        vel = (const float*)d_in[1];
        xi  = (const float*)d_in[0];
        n = in_sizes[1];
    }
    float* out = (float*)d_out;
    int blocks = (n + ROWS_PER_BLOCK - 1) / ROWS_PER_BLOCK;
    fused_kernel<<<blocks, THREADS>>>(vel, xi, out, n);
}